// round 7
// baseline (speedup 1.0000x reference)
#include <cuda_runtime.h>

#define WS    11
#define TILE  32
#define IN    42
#define NC    48

typedef unsigned long long u64;

// ---------------- packed f32x2 helpers --------------------------------------
__device__ __forceinline__ u64 pack2(float lo, float hi) {
    u64 r; asm("mov.b64 %0, {%1, %2};" : "=l"(r) : "f"(lo), "f"(hi)); return r;
}
__device__ __forceinline__ float2 unpack2(u64 v) {
    float2 f; asm("mov.b64 {%0, %1}, %2;" : "=f"(f.x), "=f"(f.y) : "l"(v)); return f;
}
__device__ __forceinline__ u64 fma2(u64 a, u64 b, u64 c) {
    u64 d; asm("fma.rn.f32x2 %0, %1, %2, %3;" : "=l"(d) : "l"(a), "l"(b), "l"(c)); return d;
}
__device__ __forceinline__ u64 add2(u64 a, u64 b) {
    u64 d; asm("add.rn.f32x2 %0, %1, %2;" : "=l"(d) : "l"(a), "l"(b)); return d;
}
__device__ __forceinline__ u64 mul2(u64 a, u64 b) {
    u64 d; asm("mul.rn.f32x2 %0, %1, %2;" : "=l"(d) : "l"(a), "l"(b)); return d;
}

// ---------------- scratch ----------------------------------------------------
__device__ float g_cs_sum[5][NC];
__device__ float g_ssim_sum[5][NC];
__device__ u64 g_s1[NC * 256 * 256];   // interleaved (x,y)
__device__ u64 g_s2[NC * 128 * 128];
__device__ u64 g_s3[NC * 64 * 64];
__device__ u64 g_s4[NC * 32 * 32];

__global__ void init_kernel() {
    int t = threadIdx.x;
    if (t < 5 * NC) { (&g_cs_sum[0][0])[t] = 0.f; (&g_ssim_sum[0][0])[t] = 0.f; }
}

// symmetric taps: w[k] == w[10-k]; 6 packed entries, read from global (broadcast)
__device__ __forceinline__ void load_taps(const float* __restrict__ win, u64* wp) {
    float inv = rsqrtf(win[5 * WS + 5]);
#pragma unroll
    for (int k = 0; k < 6; k++) { float w = win[k * WS + 5] * inv; wp[k] = pack2(w, w); }
}
#define WSYM(k) wp[(k) < 6 ? (k) : 10 - (k)]

// horizontal sliding accumulate: vals[14] -> 4 outputs x 2 planes
__device__ __forceinline__ void horiz_acc(const u64* wp, const u64* vals,
                                          u64* a1v, u64* a2v) {
#pragma unroll
    for (int j = 0; j < 14; j++) {
        u64 a = vals[j];
        float2 v = unpack2(a);
        u64 q = pack2(fmaf(v.x, v.x, v.y * v.y), v.x * v.y);
#pragma unroll
        for (int o = 0; o < 4; o++) {
            int k = j - o;
            if (k >= 0 && k < WS) {
                a1v[o] = fma2(WSYM(k), a, a1v[o]);
                a2v[o] = fma2(WSYM(k), q, a2v[o]);
            }
        }
    }
}

// vertical pass + epilogue + block reduce (swizzled hC reads)
#define SSIM_VERT_AND_REDUCE(OVAL, SCALE) \
    float ssim_acc = 0.f, cs_acc = 0.f; \
    { \
        int c = threadIdx.x; \
        int rbase = threadIdx.y * 4; \
        u64 a1v[4] = {0,0,0,0}, a2v[4] = {0,0,0,0}; \
        _Pragma("unroll") \
        for (int j = 0; j < 14; j++) { \
            int rr = rbase + j; \
            ulonglong2 hv = hC[rr][c ^ (rr & 7)]; \
            _Pragma("unroll") \
            for (int o = 0; o < 4; o++) { \
                int k = j - o; \
                if (k >= 0 && k < WS) { \
                    a1v[o] = fma2(WSYM(k), hv.x, a1v[o]); \
                    a2v[o] = fma2(WSYM(k), hv.y, a2v[o]); \
                } \
            } \
        } \
        bool colv = (ox0 + c) < (OVAL); \
        _Pragma("unroll") \
        for (int o = 0; o < 4; o++) { \
            if (colv && (oy0 + rbase + o) < (OVAL)) { \
                float2 m = unpack2(a1v[o]); \
                float2 e = unpack2(a2v[o]); \
                float mxx = m.x * m.x, myy = m.y * m.y, mxy = m.x * m.y; \
                float svar = e.x - mxx - myy; \
                float sxy_ = e.y - mxy; \
                const float C1 = 1e-4f, C2 = 9e-4f; \
                float cs = __fdividef(2.f * sxy_ + C2, svar + C2); \
                float ss = __fdividef(2.f * mxy + C1, mxx + myy + C1) * cs; \
                cs_acc += cs; ssim_acc += ss; \
            } \
        } \
    } \
    _Pragma("unroll") \
    for (int o = 16; o > 0; o >>= 1) { \
        ssim_acc += __shfl_down_sync(0xffffffffu, ssim_acc, o); \
        cs_acc   += __shfl_down_sync(0xffffffffu, cs_acc, o); \
    } \
    if (threadIdx.x == 0) { red[threadIdx.y] = ssim_acc; red[8 + threadIdx.y] = cs_acc; } \
    __syncthreads(); \
    if (tid == 0) { \
        float s = 0.f, cc = 0.f; \
        _Pragma("unroll") \
        for (int i = 0; i < 8; i++) { s += red[i]; cc += red[8 + i]; } \
        atomicAdd(&g_ssim_sum[SCALE][nc], s); \
        atomicAdd(&g_cs_sum[SCALE][nc], cc); \
    }

// ======== scale 0: fused load+horiz, vert, + pooled emission ================
__global__ __launch_bounds__(256) void ssim_scale0(
    const float* __restrict__ x0, const float* __restrict__ y0,
    const float* __restrict__ win) {
    __shared__ __align__(16) ulonglong2 hC[IN][TILE];
    __shared__ float red[16];

    int b = blockIdx.x;
    int nc = b >> 8;
    int r0 = b & 255;
    int by = r0 >> 4, bx = r0 & 15;
    const float* xb = x0 + (size_t)nc * 262144;
    const float* yb = y0 + (size_t)nc * 262144;
    int ox0 = bx * 32, oy0 = by * 32;
    int tid = threadIdx.y * 32 + threadIdx.x;

    u64 wp[6];
    load_taps(win, wp);

    // fused global load + horizontal pass: 336 tasks
    for (int t = tid; t < 336; t += 256) {
        int c0g = t / 42;
        int r   = t - c0g * 42;
        int c0  = c0g * 4;
        int gy  = oy0 + r;
        int gx0 = ox0 + c0;
        bool rowok = gy < 512;
        const float4* xr = (const float4*)(xb + (size_t)gy * 512);
        const float4* yr = (const float4*)(yb + (size_t)gy * 512);
        float4 xq[4], yq[4];
#pragma unroll
        for (int qd = 0; qd < 4; qd++) {
            int col = gx0 + 4 * qd;
            bool ok = rowok && col < 512;
            xq[qd] = ok ? xr[col >> 2] : make_float4(0.f, 0.f, 0.f, 0.f);
            yq[qd] = ok ? yr[col >> 2] : make_float4(0.f, 0.f, 0.f, 0.f);
        }
        const float* xf = (const float*)xq;
        const float* yf = (const float*)yq;
        u64 vals[14];
#pragma unroll
        for (int j = 0; j < 14; j++) vals[j] = pack2(xf[j], yf[j]);
        u64 a1v[4] = {0,0,0,0}, a2v[4] = {0,0,0,0};
        horiz_acc(wp, vals, a1v, a2v);
        int sw = r & 7;
#pragma unroll
        for (int o = 0; o < 4; o++) hC[r][(c0 + o) ^ sw] = make_ulonglong2(a1v[o], a2v[o]);
    }

    // pooled emission into g_s1 (owned 32x32 region, L2-hot re-read)
    {
        int i = tid >> 4, j = tid & 15;
        int gr = oy0 + 2 * i, gc2 = (ox0 >> 1) + j;   // float2 index
        const float2* xp0 = (const float2*)(xb + (size_t)gr * 512);
        const float2* xp1 = (const float2*)(xb + (size_t)(gr + 1) * 512);
        const float2* yp0 = (const float2*)(yb + (size_t)gr * 512);
        const float2* yp1 = (const float2*)(yb + (size_t)(gr + 1) * 512);
        float2 a = xp0[gc2], c = xp1[gc2];
        float2 e = yp0[gc2], f = yp1[gc2];
        float vx = 0.25f * ((a.x + a.y) + (c.x + c.y));
        float vy = 0.25f * ((e.x + e.y) + (f.x + f.y));
        g_s1[(size_t)nc * 65536 + (size_t)(by * 16 + i) * 256 + (bx * 16 + j)] = pack2(vx, vy);
    }
    __syncthreads();

    SSIM_VERT_AND_REDUCE(502, 0)
}

// ======== scales 1-4: fused load+horiz from u64 tables ======================
__global__ __launch_bounds__(256) void ssim_rest(const float* __restrict__ win) {
    __shared__ __align__(16) ulonglong2 hC[IN][TILE];
    __shared__ float red[16];

    int b = blockIdx.x;
    int D, O, nc, bx, by, scale;
    const u64* src;
    if (b < 3072)      { scale = 1; D = 256; O = 246; int l = b;        nc = l >> 6; int r = l & 63; by = r >> 3; bx = r & 7; src = g_s1; }
    else if (b < 3840) { scale = 2; D = 128; O = 118; int l = b - 3072; nc = l >> 4; int r = l & 15; by = r >> 2; bx = r & 3; src = g_s2; }
    else if (b < 4032) { scale = 3; D = 64;  O = 54;  int l = b - 3840; nc = l >> 2; int r = l & 3;  by = r >> 1; bx = r & 1; src = g_s3; }
    else               { scale = 4; D = 32;  O = 22;  int l = b - 4032; nc = l;      by = 0;         bx = 0;      src = g_s4; }
    src += (size_t)nc * D * D;
    int ox0 = bx * 32, oy0 = by * 32;
    int tid = threadIdx.y * 32 + threadIdx.x;

    u64 wp[6];
    load_taps(win, wp);

    for (int t = tid; t < 336; t += 256) {
        int c0g = t / 42;
        int r   = t - c0g * 42;
        int c0  = c0g * 4;
        int gy  = oy0 + r;
        int gx0 = ox0 + c0;
        bool rowok = gy < D;
        const u64* rowp = src + (size_t)gy * D;
        u64 vals[14];
#pragma unroll
        for (int jp = 0; jp < 7; jp++) {
            int col = gx0 + 2 * jp;
            bool ok = rowok && col < D;   // D even: pair fully in or fully out
            ulonglong2 pr = ok ? *(const ulonglong2*)(rowp + col)
                               : make_ulonglong2(0ull, 0ull);
            vals[2 * jp]     = pr.x;
            vals[2 * jp + 1] = pr.y;
        }
        u64 a1v[4] = {0,0,0,0}, a2v[4] = {0,0,0,0};
        horiz_acc(wp, vals, a1v, a2v);
        int sw = r & 7;
#pragma unroll
        for (int o = 0; o < 4; o++) hC[r][(c0 + o) ^ sw] = make_ulonglong2(a1v[o], a2v[o]);
    }
    __syncthreads();

    SSIM_VERT_AND_REDUCE(O, scale)
}

// ======== pool chain: s1 -> s2,s3,s4 =========================================
__global__ __launch_bounds__(256) void pool_rest() {
    __shared__ u64 s2s[32][33];
    __shared__ u64 s3s[16][17];
    int tid = threadIdx.x;
    int b = blockIdx.x;
    int nc = b >> 4;
    int r = b & 15;
    int by = r >> 2, bx = r & 3;
    const u64* s1 = g_s1 + (size_t)nc * 65536;
    u64 quarter = pack2(0.25f, 0.25f);
#pragma unroll
    for (int t = 0; t < 4; t++) {
        int o = tid + t * 256;
        int i = o >> 5, j = o & 31;
        int gr = by * 64 + 2 * i, gc = bx * 64 + 2 * j;
        u64 v = mul2(add2(add2(s1[gr * 256 + gc], s1[gr * 256 + gc + 1]),
                          add2(s1[(gr + 1) * 256 + gc], s1[(gr + 1) * 256 + gc + 1])), quarter);
        s2s[i][j] = v;
        g_s2[(size_t)nc * 16384 + (size_t)(by * 32 + i) * 128 + (bx * 32 + j)] = v;
    }
    __syncthreads();
    {
        int i = tid >> 4, j = tid & 15;
        u64 v = mul2(add2(add2(s2s[2*i][2*j], s2s[2*i][2*j+1]),
                          add2(s2s[2*i+1][2*j], s2s[2*i+1][2*j+1])), quarter);
        s3s[i][j] = v;
        g_s3[(size_t)nc * 4096 + (size_t)(by * 16 + i) * 64 + (bx * 16 + j)] = v;
    }
    __syncthreads();
    if (tid < 64) {
        int i = tid >> 3, j = tid & 7;
        u64 v = mul2(add2(add2(s3s[2*i][2*j], s3s[2*i][2*j+1]),
                          add2(s3s[2*i+1][2*j], s3s[2*i+1][2*j+1])), quarter);
        g_s4[(size_t)nc * 1024 + (size_t)(by * 8 + i) * 32 + (bx * 8 + j)] = v;
    }
}

// ---------------- final ------------------------------------------------------
__global__ void final_kernel(const float* __restrict__ weights, float* __restrict__ out) {
    __shared__ float vals[NC];
    int t = threadIdx.x;
    const int Os[5] = {502, 246, 118, 54, 22};
    if (t < NC) {
        float prod = 1.f;
#pragma unroll
        for (int s = 0; s < 5; s++) {
            float inv = 1.f / ((float)Os[s] * (float)Os[s]);
            float m = (s < 4) ? g_cs_sum[s][t] : g_ssim_sum[s][t];
            m *= inv;
            if (s < 4) m = fmaxf(m, 0.f);
            prod *= powf(m, weights[s]);
        }
        vals[t] = prod;
    }
    __syncthreads();
    if (t == 0) {
        float s = 0.f;
        for (int i = 0; i < NC; i++) s += vals[i];
        out[0] = s / (float)NC;
    }
}

// ---------------- launch -----------------------------------------------------
extern "C" void kernel_launch(void* const* d_in, const int* in_sizes, int n_in,
                              void* d_out, int out_size) {
    const float* x   = (const float*)d_in[0];
    const float* y   = (const float*)d_in[1];
    const float* win = (const float*)d_in[2];
    const float* wts = (const float*)d_in[3];
    float* out = (float*)d_out;

    init_kernel<<<1, 256>>>();
    ssim_scale0<<<12288, dim3(32, 8)>>>(x, y, win);
    pool_rest<<<768, 256>>>();
    ssim_rest<<<4080, dim3(32, 8)>>>(win);
    final_kernel<<<1, 64>>>(wts, out);
}

// round 8
// speedup vs baseline: 1.4304x; 1.4304x over previous
#include <cuda_runtime.h>

#define WS    11
#define TILE  32
#define IN    42
#define SAPAD 46
#define NC    48

typedef unsigned long long u64;

// ---------------- packed f32x2 helpers --------------------------------------
__device__ __forceinline__ u64 pack2(float lo, float hi) {
    u64 r; asm("mov.b64 %0, {%1, %2};" : "=l"(r) : "f"(lo), "f"(hi)); return r;
}
__device__ __forceinline__ float2 unpack2(u64 v) {
    float2 f; asm("mov.b64 {%0, %1}, %2;" : "=f"(f.x), "=f"(f.y) : "l"(v)); return f;
}
__device__ __forceinline__ u64 fma2(u64 a, u64 b, u64 c) {
    u64 d; asm("fma.rn.f32x2 %0, %1, %2, %3;" : "=l"(d) : "l"(a), "l"(b), "l"(c)); return d;
}
__device__ __forceinline__ u64 add2(u64 a, u64 b) {
    u64 d; asm("add.rn.f32x2 %0, %1, %2;" : "=l"(d) : "l"(a), "l"(b)); return d;
}
__device__ __forceinline__ u64 mul2(u64 a, u64 b) {
    u64 d; asm("mul.rn.f32x2 %0, %1, %2;" : "=l"(d) : "l"(a), "l"(b)); return d;
}

// ---------------- scratch ----------------------------------------------------
__device__ float g_cs_sum[5][NC];
__device__ float g_ssim_sum[5][NC];
__device__ u64 g_s1[NC * 256 * 256];   // interleaved (x,y)
__device__ u64 g_s2[NC * 128 * 128];
__device__ u64 g_s3[NC * 64 * 64];
__device__ u64 g_s4[NC * 32 * 32];

__global__ void init_kernel() {
    int t = threadIdx.x;
    if (t < 5 * NC) { (&g_cs_sum[0][0])[t] = 0.f; (&g_ssim_sum[0][0])[t] = 0.f; }
}

// ======== ssim core pieces ===================================================
#define SSIM_SHARED \
    __shared__ __align__(16) u64 sA[IN][SAPAD]; \
    __shared__ __align__(16) ulonglong2 hC[IN][TILE]; \
    __shared__ float tg_s[WS]; \
    __shared__ float red[16];

#define SSIM_TAPS \
    if (tid < WS) tg_s[tid] = win[tid * WS + 5] * rsqrtf(win[5 * WS + 5]);

// symmetric taps: w[k] == w[10-k]
#define SSIM_WP \
    u64 wp[6]; \
    _Pragma("unroll") \
    for (int k = 0; k < 6; k++) { float w = tg_s[k]; wp[k] = pack2(w, w); }

#define WSYM(k) wp[(k) < 6 ? (k) : 10 - (k)]

// horizontal: tasks t in [0,336): r = t%42, c0 = (t/42)*4; 7 LDS.128 -> 4 outputs
// hC write swizzled: col ^ (r & 7)
#define SSIM_HORIZ \
    for (int t = tid; t < 336; t += 256) { \
        int c0g = t / 42; \
        int r   = t - c0g * 42; \
        int c0  = c0g * 4; \
        u64 a1v[4] = {0,0,0,0}, a2v[4] = {0,0,0,0}; \
        const ulonglong2* rowp = (const ulonglong2*)&sA[r][0]; \
        _Pragma("unroll") \
        for (int jp = 0; jp < 7; jp++) { \
            ulonglong2 pr = rowp[(c0 >> 1) + jp]; \
            _Pragma("unroll") \
            for (int e = 0; e < 2; e++) { \
                int j = 2 * jp + e; \
                u64 a = e ? pr.y : pr.x; \
                float2 v = unpack2(a); \
                u64 q = pack2(fmaf(v.x, v.x, v.y * v.y), v.x * v.y); \
                _Pragma("unroll") \
                for (int o = 0; o < 4; o++) { \
                    int k = j - o; \
                    if (k >= 0 && k < WS) { \
                        a1v[o] = fma2(WSYM(k), a, a1v[o]); \
                        a2v[o] = fma2(WSYM(k), q, a2v[o]); \
                    } \
                } \
            } \
        } \
        int sw = r & 7; \
        _Pragma("unroll") \
        for (int o = 0; o < 4; o++) hC[r][(c0 + o) ^ sw] = make_ulonglong2(a1v[o], a2v[o]); \
    }

// vertical: all 256 threads, 4 output rows each; 14 LDS.128 (swizzled cols)
#define SSIM_VERT_AND_REDUCE(OVAL, SCALE) \
    float ssim_acc = 0.f, cs_acc = 0.f; \
    { \
        int c = threadIdx.x; \
        int rbase = threadIdx.y * 4; \
        u64 a1v[4] = {0,0,0,0}, a2v[4] = {0,0,0,0}; \
        _Pragma("unroll") \
        for (int j = 0; j < 14; j++) { \
            int rr = rbase + j; \
            ulonglong2 hv = hC[rr][c ^ (rr & 7)]; \
            _Pragma("unroll") \
            for (int o = 0; o < 4; o++) { \
                int k = j - o; \
                if (k >= 0 && k < WS) { \
                    a1v[o] = fma2(WSYM(k), hv.x, a1v[o]); \
                    a2v[o] = fma2(WSYM(k), hv.y, a2v[o]); \
                } \
            } \
        } \
        bool colv = (ox0 + c) < (OVAL); \
        _Pragma("unroll") \
        for (int o = 0; o < 4; o++) { \
            if (colv && (oy0 + rbase + o) < (OVAL)) { \
                float2 m = unpack2(a1v[o]); \
                float2 e = unpack2(a2v[o]); \
                float mxx = m.x * m.x, myy = m.y * m.y, mxy = m.x * m.y; \
                float svar = e.x - mxx - myy; \
                float sxy_ = e.y - mxy; \
                const float C1 = 1e-4f, C2 = 9e-4f; \
                float cs = __fdividef(2.f * sxy_ + C2, svar + C2); \
                float ss = __fdividef(2.f * mxy + C1, mxx + myy + C1) * cs; \
                cs_acc += cs; ssim_acc += ss; \
            } \
        } \
    } \
    _Pragma("unroll") \
    for (int o = 16; o > 0; o >>= 1) { \
        ssim_acc += __shfl_down_sync(0xffffffffu, ssim_acc, o); \
        cs_acc   += __shfl_down_sync(0xffffffffu, cs_acc, o); \
    } \
    if (threadIdx.x == 0) { red[threadIdx.y] = ssim_acc; red[8 + threadIdx.y] = cs_acc; } \
    __syncthreads(); \
    if (tid == 0) { \
        float s = 0.f, cc = 0.f; \
        _Pragma("unroll") \
        for (int i = 0; i < 8; i++) { s += red[i]; cc += red[8 + i]; } \
        atomicAdd(&g_ssim_sum[SCALE][nc], s); \
        atomicAdd(&g_cs_sum[SCALE][nc], cc); \
    }

// ======== scale 0: ssim + pooled emission into g_s1 =========================
__global__ __launch_bounds__(256, 6) void ssim_scale0(
    const float* __restrict__ x0, const float* __restrict__ y0,
    const float* __restrict__ win) {
    SSIM_SHARED
    int b = blockIdx.x;
    int nc = b >> 8;
    int r0 = b & 255;
    int by = r0 >> 4, bx = r0 & 15;
    const float* xb = x0 + (size_t)nc * 262144;
    const float* yb = y0 + (size_t)nc * 262144;
    int ox0 = bx * 32, oy0 = by * 32;
    int tid = threadIdx.y * 32 + threadIdx.x;

    SSIM_TAPS

    for (int idx = tid; idx < IN * IN; idx += 256) {
        int r = idx / IN, c = idx - r * IN;
        int gy = oy0 + r, gx = ox0 + c;
        float xv = 0.f, yv = 0.f;
        if (gy < 512 && gx < 512) { xv = xb[gy * 512 + gx]; yv = yb[gy * 512 + gx]; }
        sA[r][c] = pack2(xv, yv);
    }
    __syncthreads();

    SSIM_WP
    SSIM_HORIZ

    // pooled emission: owned 32x32 -> 16x16 of scale-1 (reads stable sA)
    {
        int i = tid >> 4, j = tid & 15;
        u64 s = add2(add2(sA[2*i][2*j], sA[2*i][2*j+1]),
                     add2(sA[2*i+1][2*j], sA[2*i+1][2*j+1]));
        s = mul2(s, pack2(0.25f, 0.25f));
        g_s1[(size_t)nc * 65536 + (size_t)(by * 16 + i) * 256 + (bx * 16 + j)] = s;
    }
    __syncthreads();

    SSIM_VERT_AND_REDUCE(502, 0)
}

// ======== scales 1-4 =========================================================
__global__ __launch_bounds__(256, 6) void ssim_rest(const float* __restrict__ win) {
    SSIM_SHARED
    int b = blockIdx.x;
    int D, O, nc, bx, by, scale;
    const u64* src;
    if (b < 3072)      { scale = 1; D = 256; O = 246; int l = b;        nc = l >> 6; int r = l & 63; by = r >> 3; bx = r & 7; src = g_s1; }
    else if (b < 3840) { scale = 2; D = 128; O = 118; int l = b - 3072; nc = l >> 4; int r = l & 15; by = r >> 2; bx = r & 3; src = g_s2; }
    else if (b < 4032) { scale = 3; D = 64;  O = 54;  int l = b - 3840; nc = l >> 2; int r = l & 3;  by = r >> 1; bx = r & 1; src = g_s3; }
    else               { scale = 4; D = 32;  O = 22;  int l = b - 4032; nc = l;      by = 0;         bx = 0;      src = g_s4; }
    src += (size_t)nc * D * D;
    int ox0 = bx * 32, oy0 = by * 32;
    int tid = threadIdx.y * 32 + threadIdx.x;

    SSIM_TAPS

    for (int idx = tid; idx < IN * IN; idx += 256) {
        int r = idx / IN, c = idx - r * IN;
        int gy = oy0 + r, gx = ox0 + c;
        sA[r][c] = (gy < D && gx < D) ? src[gy * D + gx] : 0ull;
    }
    __syncthreads();

    SSIM_WP
    SSIM_HORIZ
    __syncthreads();

    SSIM_VERT_AND_REDUCE(O, scale)
}

// ======== pool chain: s1 -> s2,s3,s4 =========================================
__global__ __launch_bounds__(256) void pool_rest() {
    __shared__ u64 s2s[32][33];
    __shared__ u64 s3s[16][17];
    int tid = threadIdx.x;
    int b = blockIdx.x;
    int nc = b >> 4;
    int r = b & 15;
    int by = r >> 2, bx = r & 3;
    const u64* s1 = g_s1 + (size_t)nc * 65536;
    u64 quarter = pack2(0.25f, 0.25f);
#pragma unroll
    for (int t = 0; t < 4; t++) {
        int o = tid + t * 256;
        int i = o >> 5, j = o & 31;
        int gr = by * 64 + 2 * i, gc = bx * 64 + 2 * j;
        u64 v = mul2(add2(add2(s1[gr * 256 + gc], s1[gr * 256 + gc + 1]),
                          add2(s1[(gr + 1) * 256 + gc], s1[(gr + 1) * 256 + gc + 1])), quarter);
        s2s[i][j] = v;
        g_s2[(size_t)nc * 16384 + (size_t)(by * 32 + i) * 128 + (bx * 32 + j)] = v;
    }
    __syncthreads();
    {
        int i = tid >> 4, j = tid & 15;
        u64 v = mul2(add2(add2(s2s[2*i][2*j], s2s[2*i][2*j+1]),
                          add2(s2s[2*i+1][2*j], s2s[2*i+1][2*j+1])), quarter);
        s3s[i][j] = v;
        g_s3[(size_t)nc * 4096 + (size_t)(by * 16 + i) * 64 + (bx * 16 + j)] = v;
    }
    __syncthreads();
    if (tid < 64) {
        int i = tid >> 3, j = tid & 7;
        u64 v = mul2(add2(add2(s3s[2*i][2*j], s3s[2*i][2*j+1]),
                          add2(s3s[2*i+1][2*j], s3s[2*i+1][2*j+1])), quarter);
        g_s4[(size_t)nc * 1024 + (size_t)(by * 8 + i) * 32 + (bx * 8 + j)] = v;
    }
}

// ---------------- final ------------------------------------------------------
__global__ void final_kernel(const float* __restrict__ weights, float* __restrict__ out) {
    __shared__ float vals[NC];
    int t = threadIdx.x;
    const int Os[5] = {502, 246, 118, 54, 22};
    if (t < NC) {
        float prod = 1.f;
#pragma unroll
        for (int s = 0; s < 5; s++) {
            float inv = 1.f / ((float)Os[s] * (float)Os[s]);
            float m = (s < 4) ? g_cs_sum[s][t] : g_ssim_sum[s][t];
            m *= inv;
            if (s < 4) m = fmaxf(m, 0.f);
            prod *= powf(m, weights[s]);
        }
        vals[t] = prod;
    }
    __syncthreads();
    if (t == 0) {
        float s = 0.f;
        for (int i = 0; i < NC; i++) s += vals[i];
        out[0] = s / (float)NC;
    }
}

// ---------------- launch -----------------------------------------------------
extern "C" void kernel_launch(void* const* d_in, const int* in_sizes, int n_in,
                              void* d_out, int out_size) {
    const float* x   = (const float*)d_in[0];
    const float* y   = (const float*)d_in[1];
    const float* win = (const float*)d_in[2];
    const float* wts = (const float*)d_in[3];
    float* out = (float*)d_out;

    init_kernel<<<1, 256>>>();
    ssim_scale0<<<12288, dim3(32, 8)>>>(x, y, win);
    pool_rest<<<768, 256>>>();
    ssim_rest<<<4080, dim3(32, 8)>>>(win);
    final_kernel<<<1, 64>>>(wts, out);
}

// round 9
// speedup vs baseline: 1.7962x; 1.2558x over previous
#include <cuda_runtime.h>

#define WS    11
#define TILE  32
#define IN    42
#define SAPAD 46
#define HPAD  33
#define NC    48

typedef unsigned long long u64;

// ---------------- packed f32x2 helpers --------------------------------------
__device__ __forceinline__ u64 pack2(float lo, float hi) {
    u64 r; asm("mov.b64 %0, {%1, %2};" : "=l"(r) : "f"(lo), "f"(hi)); return r;
}
__device__ __forceinline__ float2 unpack2(u64 v) {
    float2 f; asm("mov.b64 {%0, %1}, %2;" : "=f"(f.x), "=f"(f.y) : "l"(v)); return f;
}
__device__ __forceinline__ u64 fma2(u64 a, u64 b, u64 c) {
    u64 d; asm("fma.rn.f32x2 %0, %1, %2, %3;" : "=l"(d) : "l"(a), "l"(b), "l"(c)); return d;
}
__device__ __forceinline__ u64 add2(u64 a, u64 b) {
    u64 d; asm("add.rn.f32x2 %0, %1, %2;" : "=l"(d) : "l"(a), "l"(b)); return d;
}
__device__ __forceinline__ u64 mul2(u64 a, u64 b) {
    u64 d; asm("mul.rn.f32x2 %0, %1, %2;" : "=l"(d) : "l"(a), "l"(b)); return d;
}

// ---------------- scratch ----------------------------------------------------
__device__ float g_cs_sum[5][NC];
__device__ float g_ssim_sum[5][NC];
__device__ u64 g_s1[NC * 256 * 256];   // interleaved (x,y)
__device__ u64 g_s2[NC * 128 * 128];
__device__ u64 g_s3[NC * 64 * 64];
__device__ u64 g_s4[NC * 32 * 32];

__global__ void init_kernel() {
    int t = threadIdx.x;
    if (t < 5 * NC) { (&g_cs_sum[0][0])[t] = 0.f; (&g_ssim_sum[0][0])[t] = 0.f; }
}

// ======== ssim core pieces ===================================================
#define SSIM_SHARED \
    __shared__ __align__(16) u64 sA[IN][SAPAD]; \
    __shared__ __align__(16) ulonglong2 hC[IN][HPAD]; \
    __shared__ float tg_s[WS]; \
    __shared__ float red[16];

#define SSIM_TAPS \
    if (tid < WS) tg_s[tid] = win[tid * WS + 5] * rsqrtf(win[5 * WS + 5]);

// symmetric taps: w[k] == w[10-k]
#define SSIM_WP \
    u64 wp[6]; \
    _Pragma("unroll") \
    for (int k = 0; k < 6; k++) { float w = tg_s[k]; wp[k] = pack2(w, w); }

#define WSYM(k) wp[(k) < 6 ? (k) : 10 - (k)]

// one horizontal task: r = t%42, c0 = (t/42)*4; 7 LDS.128 -> 4 outputs
#define SSIM_HORIZ_TASK(t) { \
    int c0g = (t) / 42; \
    int r   = (t) - c0g * 42; \
    int c0  = c0g * 4; \
    u64 a1v[4] = {0,0,0,0}, a2v[4] = {0,0,0,0}; \
    const ulonglong2* rowp = (const ulonglong2*)&sA[r][0]; \
    _Pragma("unroll") \
    for (int jp = 0; jp < 7; jp++) { \
        ulonglong2 pr = rowp[(c0 >> 1) + jp]; \
        _Pragma("unroll") \
        for (int e = 0; e < 2; e++) { \
            int j = 2 * jp + e; \
            u64 a = e ? pr.y : pr.x; \
            float2 v = unpack2(a); \
            u64 q = pack2(fmaf(v.x, v.x, v.y * v.y), v.x * v.y); \
            _Pragma("unroll") \
            for (int o = 0; o < 4; o++) { \
                int k = j - o; \
                if (k >= 0 && k < WS) { \
                    a1v[o] = fma2(WSYM(k), a, a1v[o]); \
                    a2v[o] = fma2(WSYM(k), q, a2v[o]); \
                } \
            } \
        } \
    } \
    _Pragma("unroll") \
    for (int o = 0; o < 4; o++) hC[r][c0 + o] = make_ulonglong2(a1v[o], a2v[o]); \
}

// vertical: all 256 threads, 4 output rows each; 14 LDS.128 (padded, no swizzle)
#define SSIM_VERT_AND_REDUCE(OVAL, SCALE) \
    float ssim_acc = 0.f, cs_acc = 0.f; \
    { \
        int c = threadIdx.x; \
        int rbase = threadIdx.y * 4; \
        u64 a1v[4] = {0,0,0,0}, a2v[4] = {0,0,0,0}; \
        _Pragma("unroll") \
        for (int j = 0; j < 14; j++) { \
            ulonglong2 hv = hC[rbase + j][c]; \
            _Pragma("unroll") \
            for (int o = 0; o < 4; o++) { \
                int k = j - o; \
                if (k >= 0 && k < WS) { \
                    a1v[o] = fma2(WSYM(k), hv.x, a1v[o]); \
                    a2v[o] = fma2(WSYM(k), hv.y, a2v[o]); \
                } \
            } \
        } \
        bool colv = (ox0 + c) < (OVAL); \
        _Pragma("unroll") \
        for (int o = 0; o < 4; o++) { \
            if (colv && (oy0 + rbase + o) < (OVAL)) { \
                float2 m = unpack2(a1v[o]); \
                float2 e = unpack2(a2v[o]); \
                float mxx = m.x * m.x, myy = m.y * m.y, mxy = m.x * m.y; \
                float svar = e.x - mxx - myy; \
                float sxy_ = e.y - mxy; \
                const float C1 = 1e-4f, C2 = 9e-4f; \
                float cs = __fdividef(2.f * sxy_ + C2, svar + C2); \
                float ss = __fdividef(2.f * mxy + C1, mxx + myy + C1) * cs; \
                cs_acc += cs; ssim_acc += ss; \
            } \
        } \
    } \
    _Pragma("unroll") \
    for (int o = 16; o > 0; o >>= 1) { \
        ssim_acc += __shfl_down_sync(0xffffffffu, ssim_acc, o); \
        cs_acc   += __shfl_down_sync(0xffffffffu, cs_acc, o); \
    } \
    if (threadIdx.x == 0) { red[threadIdx.y] = ssim_acc; red[8 + threadIdx.y] = cs_acc; } \
    __syncthreads(); \
    if (tid == 0) { \
        float s = 0.f, cc = 0.f; \
        _Pragma("unroll") \
        for (int i = 0; i < 8; i++) { s += red[i]; cc += red[8 + i]; } \
        atomicAdd(&g_ssim_sum[SCALE][nc], s); \
        atomicAdd(&g_cs_sum[SCALE][nc], cc); \
    }

// ======== scale 0: ssim + pooled emission into g_s1 =========================
__global__ __launch_bounds__(256, 6) void ssim_scale0(
    const float* __restrict__ x0, const float* __restrict__ y0,
    const float* __restrict__ win) {
    SSIM_SHARED
    int b = blockIdx.x;
    int nc = b >> 8;
    int r0 = b & 255;
    int by = r0 >> 4, bx = r0 & 15;
    const float* xb = x0 + (size_t)nc * 262144;
    const float* yb = y0 + (size_t)nc * 262144;
    int ox0 = bx * 32, oy0 = by * 32;
    int tid = threadIdx.y * 32 + threadIdx.x;

    SSIM_TAPS

    // vectorized staging: 462 tasks, each loads 4 cols via float4, packs to sA
#pragma unroll
    for (int it = 0; it < 2; it++) {
        int t = tid + it * 256;
        if (t < 462) {
            int r = t / 11;
            int g = t - r * 11;
            int gy = oy0 + r;
            int gxq = ox0 + g * 4;
            float4 xq = make_float4(0.f, 0.f, 0.f, 0.f), yq = xq;
            if (gy < 512 && gxq < 512) {
                xq = *(const float4*)(xb + (size_t)gy * 512 + gxq);
                yq = *(const float4*)(yb + (size_t)gy * 512 + gxq);
            }
            ulonglong2* dst = (ulonglong2*)&sA[r][g * 4];
            dst[0] = make_ulonglong2(pack2(xq.x, yq.x), pack2(xq.y, yq.y));
            dst[1] = make_ulonglong2(pack2(xq.z, yq.z), pack2(xq.w, yq.w));
        }
    }
    __syncthreads();

    SSIM_WP
    SSIM_HORIZ_TASK(tid)
    if (tid < 80) {
        SSIM_HORIZ_TASK(tid + 256)
    } else if (tid >= 96) {
        // pooled emission by warps 3-7 (balances warps 0-2's second horiz task)
#pragma unroll
        for (int p = tid - 96; p < 256; p += 160) {
            int i = p >> 4, j = p & 15;
            u64 s = add2(add2(sA[2*i][2*j], sA[2*i][2*j+1]),
                         add2(sA[2*i+1][2*j], sA[2*i+1][2*j+1]));
            s = mul2(s, pack2(0.25f, 0.25f));
            g_s1[(size_t)nc * 65536 + (size_t)(by * 16 + i) * 256 + (bx * 16 + j)] = s;
        }
    }
    __syncthreads();

    SSIM_VERT_AND_REDUCE(502, 0)
}

// ======== scales 1-4 =========================================================
__global__ __launch_bounds__(256, 6) void ssim_rest(const float* __restrict__ win) {
    SSIM_SHARED
    int b = blockIdx.x;
    int D, O, nc, bx, by, scale;
    const u64* src;
    if (b < 3072)      { scale = 1; D = 256; O = 246; int l = b;        nc = l >> 6; int r = l & 63; by = r >> 3; bx = r & 7; src = g_s1; }
    else if (b < 3840) { scale = 2; D = 128; O = 118; int l = b - 3072; nc = l >> 4; int r = l & 15; by = r >> 2; bx = r & 3; src = g_s2; }
    else if (b < 4032) { scale = 3; D = 64;  O = 54;  int l = b - 3840; nc = l >> 2; int r = l & 3;  by = r >> 1; bx = r & 1; src = g_s3; }
    else               { scale = 4; D = 32;  O = 22;  int l = b - 4032; nc = l;      by = 0;         bx = 0;      src = g_s4; }
    src += (size_t)nc * D * D;
    int ox0 = bx * 32, oy0 = by * 32;
    int tid = threadIdx.y * 32 + threadIdx.x;

    SSIM_TAPS

    // vectorized staging: 462 tasks, each 4 u64 cols via 2 LDG.128
#pragma unroll
    for (int it = 0; it < 2; it++) {
        int t = tid + it * 256;
        if (t < 462) {
            int r = t / 11;
            int g = t - r * 11;
            int gy = oy0 + r;
            int gxq = ox0 + g * 4;
            ulonglong2 p0 = make_ulonglong2(0ull, 0ull), p1 = p0;
            if (gy < D && gxq < D) {   // D,gxq multiples of 4: quad fully in-range
                const ulonglong2* rp = (const ulonglong2*)(src + (size_t)gy * D + gxq);
                p0 = rp[0]; p1 = rp[1];
            }
            ulonglong2* dst = (ulonglong2*)&sA[r][g * 4];
            dst[0] = p0; dst[1] = p1;
        }
    }
    __syncthreads();

    SSIM_WP
    SSIM_HORIZ_TASK(tid)
    if (tid < 80) SSIM_HORIZ_TASK(tid + 256)
    __syncthreads();

    SSIM_VERT_AND_REDUCE(O, scale)
}

// ======== pool chain: s1 -> s2,s3,s4 =========================================
__global__ __launch_bounds__(256) void pool_rest() {
    __shared__ u64 s2s[32][33];
    __shared__ u64 s3s[16][17];
    int tid = threadIdx.x;
    int b = blockIdx.x;
    int nc = b >> 4;
    int r = b & 15;
    int by = r >> 2, bx = r & 3;
    const u64* s1 = g_s1 + (size_t)nc * 65536;
    u64 quarter = pack2(0.25f, 0.25f);
#pragma unroll
    for (int t = 0; t < 4; t++) {
        int o = tid + t * 256;
        int i = o >> 5, j = o & 31;
        int gr = by * 64 + 2 * i, gc = bx * 64 + 2 * j;
        u64 v = mul2(add2(add2(s1[gr * 256 + gc], s1[gr * 256 + gc + 1]),
                          add2(s1[(gr + 1) * 256 + gc], s1[(gr + 1) * 256 + gc + 1])), quarter);
        s2s[i][j] = v;
        g_s2[(size_t)nc * 16384 + (size_t)(by * 32 + i) * 128 + (bx * 32 + j)] = v;
    }
    __syncthreads();
    {
        int i = tid >> 4, j = tid & 15;
        u64 v = mul2(add2(add2(s2s[2*i][2*j], s2s[2*i][2*j+1]),
                          add2(s2s[2*i+1][2*j], s2s[2*i+1][2*j+1])), quarter);
        s3s[i][j] = v;
        g_s3[(size_t)nc * 4096 + (size_t)(by * 16 + i) * 64 + (bx * 16 + j)] = v;
    }
    __syncthreads();
    if (tid < 64) {
        int i = tid >> 3, j = tid & 7;
        u64 v = mul2(add2(add2(s3s[2*i][2*j], s3s[2*i][2*j+1]),
                          add2(s3s[2*i+1][2*j], s3s[2*i+1][2*j+1])), quarter);
        g_s4[(size_t)nc * 1024 + (size_t)(by * 8 + i) * 32 + (bx * 8 + j)] = v;
    }
}

// ---------------- final ------------------------------------------------------
__global__ void final_kernel(const float* __restrict__ weights, float* __restrict__ out) {
    __shared__ float vals[NC];
    int t = threadIdx.x;
    const int Os[5] = {502, 246, 118, 54, 22};
    if (t < NC) {
        float prod = 1.f;
#pragma unroll
        for (int s = 0; s < 5; s++) {
            float inv = 1.f / ((float)Os[s] * (float)Os[s]);
            float m = (s < 4) ? g_cs_sum[s][t] : g_ssim_sum[s][t];
            m *= inv;
            if (s < 4) m = fmaxf(m, 0.f);
            prod *= powf(m, weights[s]);
        }
        vals[t] = prod;
    }
    __syncthreads();
    if (t == 0) {
        float s = 0.f;
        for (int i = 0; i < NC; i++) s += vals[i];
        out[0] = s / (float)NC;
    }
}

// ---------------- launch -----------------------------------------------------
extern "C" void kernel_launch(void* const* d_in, const int* in_sizes, int n_in,
                              void* d_out, int out_size) {
    const float* x   = (const float*)d_in[0];
    const float* y   = (const float*)d_in[1];
    const float* win = (const float*)d_in[2];
    const float* wts = (const float*)d_in[3];
    float* out = (float*)d_out;

    init_kernel<<<1, 256>>>();
    ssim_scale0<<<12288, dim3(32, 8)>>>(x, y, win);
    pool_rest<<<768, 256>>>();
    ssim_rest<<<4080, dim3(32, 8)>>>(win);
    final_kernel<<<1, 64>>>(wts, out);
}

// round 10
// speedup vs baseline: 1.8317x; 1.0197x over previous
#include <cuda_runtime.h>

#define WS    11
#define TILE  32
#define IN    42
#define SAPAD 46
#define HPAD  33
#define NC    48

#define SA_BYTES (IN * SAPAD * 8)      // 15456
#define HC_BYTES (IN * HPAD * 16)      // 22176

typedef unsigned long long u64;

// ---------------- packed f32x2 helpers --------------------------------------
__device__ __forceinline__ u64 pack2(float lo, float hi) {
    u64 r; asm("mov.b64 %0, {%1, %2};" : "=l"(r) : "f"(lo), "f"(hi)); return r;
}
__device__ __forceinline__ float2 unpack2(u64 v) {
    float2 f; asm("mov.b64 {%0, %1}, %2;" : "=f"(f.x), "=f"(f.y) : "l"(v)); return f;
}
__device__ __forceinline__ u64 fma2(u64 a, u64 b, u64 c) {
    u64 d; asm("fma.rn.f32x2 %0, %1, %2, %3;" : "=l"(d) : "l"(a), "l"(b), "l"(c)); return d;
}
__device__ __forceinline__ u64 add2(u64 a, u64 b) {
    u64 d; asm("add.rn.f32x2 %0, %1, %2;" : "=l"(d) : "l"(a), "l"(b)); return d;
}
__device__ __forceinline__ u64 mul2(u64 a, u64 b) {
    u64 d; asm("mul.rn.f32x2 %0, %1, %2;" : "=l"(d) : "l"(a), "l"(b)); return d;
}

// ---------------- scratch ----------------------------------------------------
__device__ float g_cs_sum[5][NC];
__device__ float g_ssim_sum[5][NC];
__device__ u64 g_s1[NC * 256 * 256];   // interleaved (x,y)
__device__ u64 g_s2[NC * 128 * 128];
__device__ u64 g_s3[NC * 64 * 64];
__device__ u64 g_s4[NC * 32 * 32];

__global__ void init_kernel() {
    int t = threadIdx.x;
    if (t < 5 * NC) { (&g_cs_sum[0][0])[t] = 0.f; (&g_ssim_sum[0][0])[t] = 0.f; }
}

// ======== ssim core pieces ===================================================
// sA and hC live in one raw region; hC is dead after the vertical pass and is
// reused as pool scratch in scale0's tail.
#define SSIM_SHARED \
    __shared__ __align__(16) char smem_raw[SA_BYTES + HC_BYTES]; \
    u64 (*sA)[SAPAD] = reinterpret_cast<u64(*)[SAPAD]>(smem_raw); \
    ulonglong2 (*hC)[HPAD] = reinterpret_cast<ulonglong2(*)[HPAD]>(smem_raw + SA_BYTES); \
    __shared__ float tg_s[WS]; \
    __shared__ float red[16];

#define SSIM_TAPS \
    if (tid < WS) tg_s[tid] = win[tid * WS + 5] * rsqrtf(win[5 * WS + 5]);

// symmetric taps: w[k] == w[10-k]
#define SSIM_WP \
    u64 wp[6]; \
    _Pragma("unroll") \
    for (int k = 0; k < 6; k++) { float w = tg_s[k]; wp[k] = pack2(w, w); }

#define WSYM(k) wp[(k) < 6 ? (k) : 10 - (k)]

// one horizontal task: r = t%42, c0 = (t/42)*4; 7 LDS.128 -> 4 outputs.
// software-pipelined: prefetch next pair before consuming current.
#define SSIM_HORIZ_TASK(t) { \
    int c0g = (t) / 42; \
    int r   = (t) - c0g * 42; \
    int c0  = c0g * 4; \
    u64 a1v[4] = {0,0,0,0}, a2v[4] = {0,0,0,0}; \
    const ulonglong2* hp = (const ulonglong2*)&sA[r][0] + (c0 >> 1); \
    ulonglong2 pr = hp[0]; \
    _Pragma("unroll") \
    for (int jp = 0; jp < 7; jp++) { \
        ulonglong2 nxt; \
        if (jp < 6) nxt = hp[jp + 1]; \
        _Pragma("unroll") \
        for (int e = 0; e < 2; e++) { \
            int j = 2 * jp + e; \
            u64 a = e ? pr.y : pr.x; \
            float2 v = unpack2(a); \
            u64 q = pack2(fmaf(v.x, v.x, v.y * v.y), v.x * v.y); \
            _Pragma("unroll") \
            for (int o = 0; o < 4; o++) { \
                int k = j - o; \
                if (k >= 0 && k < WS) { \
                    a1v[o] = fma2(WSYM(k), a, a1v[o]); \
                    a2v[o] = fma2(WSYM(k), q, a2v[o]); \
                } \
            } \
        } \
        pr = nxt; \
    } \
    _Pragma("unroll") \
    for (int o = 0; o < 4; o++) hC[r][c0 + o] = make_ulonglong2(a1v[o], a2v[o]); \
}

// vertical: all 256 threads, 4 output rows each; 14 LDS.128, pipelined.
#define SSIM_VERT_AND_REDUCE(OVAL, SCALE) \
    float ssim_acc = 0.f, cs_acc = 0.f; \
    { \
        int c = threadIdx.x; \
        int rbase = threadIdx.y * 4; \
        u64 a1v[4] = {0,0,0,0}, a2v[4] = {0,0,0,0}; \
        const ulonglong2* vp = &hC[rbase][c]; \
        ulonglong2 hv = vp[0]; \
        _Pragma("unroll") \
        for (int j = 0; j < 14; j++) { \
            ulonglong2 nxt; \
            if (j < 13) nxt = vp[(j + 1) * HPAD]; \
            _Pragma("unroll") \
            for (int o = 0; o < 4; o++) { \
                int k = j - o; \
                if (k >= 0 && k < WS) { \
                    a1v[o] = fma2(WSYM(k), hv.x, a1v[o]); \
                    a2v[o] = fma2(WSYM(k), hv.y, a2v[o]); \
                } \
            } \
            hv = nxt; \
        } \
        bool colv = (ox0 + c) < (OVAL); \
        _Pragma("unroll") \
        for (int o = 0; o < 4; o++) { \
            if (colv && (oy0 + rbase + o) < (OVAL)) { \
                float2 m = unpack2(a1v[o]); \
                float2 e = unpack2(a2v[o]); \
                float mxx = m.x * m.x, myy = m.y * m.y, mxy = m.x * m.y; \
                float svar = e.x - mxx - myy; \
                float sxy_ = e.y - mxy; \
                const float C1 = 1e-4f, C2 = 9e-4f; \
                float cs = __fdividef(2.f * sxy_ + C2, svar + C2); \
                float ss = __fdividef(2.f * mxy + C1, mxx + myy + C1) * cs; \
                cs_acc += cs; ssim_acc += ss; \
            } \
        } \
    } \
    _Pragma("unroll") \
    for (int o = 16; o > 0; o >>= 1) { \
        ssim_acc += __shfl_down_sync(0xffffffffu, ssim_acc, o); \
        cs_acc   += __shfl_down_sync(0xffffffffu, cs_acc, o); \
    } \
    if (threadIdx.x == 0) { red[threadIdx.y] = ssim_acc; red[8 + threadIdx.y] = cs_acc; } \
    __syncthreads(); \
    if (tid == 0) { \
        float s = 0.f, cc = 0.f; \
        _Pragma("unroll") \
        for (int i = 0; i < 8; i++) { s += red[i]; cc += red[8 + i]; } \
        atomicAdd(&g_ssim_sum[SCALE][nc], s); \
        atomicAdd(&g_cs_sum[SCALE][nc], cc); \
    }

// ======== scale 0: ssim + full pool chain in the tail =======================
__global__ __launch_bounds__(256, 6) void ssim_scale0(
    const float* __restrict__ x0, const float* __restrict__ y0,
    const float* __restrict__ win) {
    SSIM_SHARED
    int b = blockIdx.x;
    int nc = b >> 8;
    int r0 = b & 255;
    int by = r0 >> 4, bx = r0 & 15;
    const float* xb = x0 + (size_t)nc * 262144;
    const float* yb = y0 + (size_t)nc * 262144;
    int ox0 = bx * 32, oy0 = by * 32;
    int tid = threadIdx.y * 32 + threadIdx.x;

    SSIM_TAPS

    // vectorized staging: 462 tasks, each loads 4 cols via float4, packs to sA
#pragma unroll
    for (int it = 0; it < 2; it++) {
        int t = tid + it * 256;
        if (t < 462) {
            int r = t / 11;
            int g = t - r * 11;
            int gy = oy0 + r;
            int gxq = ox0 + g * 4;
            float4 xq = make_float4(0.f, 0.f, 0.f, 0.f), yq = xq;
            if (gy < 512 && gxq < 512) {
                xq = *(const float4*)(xb + (size_t)gy * 512 + gxq);
                yq = *(const float4*)(yb + (size_t)gy * 512 + gxq);
            }
            ulonglong2* dst = (ulonglong2*)&sA[r][g * 4];
            dst[0] = make_ulonglong2(pack2(xq.x, yq.x), pack2(xq.y, yq.y));
            dst[1] = make_ulonglong2(pack2(xq.z, yq.z), pack2(xq.w, yq.w));
        }
    }
    __syncthreads();

    SSIM_WP
    SSIM_HORIZ_TASK(tid)
    if (tid < 80) SSIM_HORIZ_TASK(tid + 256)
    __syncthreads();

    SSIM_VERT_AND_REDUCE(502, 0)

    // ---- pool chain tail: sA is intact; hC is dead -> reuse as scratch ----
    u64* scr1 = (u64*)(smem_raw + SA_BYTES);        // 256 u64
    u64* scr2 = scr1 + 256;                          // 64 u64
    u64* scr3 = scr2 + 64;                           // 16 u64
    u64 quarter = pack2(0.25f, 0.25f);
    // (the reduce barrier above guarantees all hC reads are complete)
    {
        int i = tid >> 4, j = tid & 15;
        u64 s = mul2(add2(add2(sA[2*i][2*j], sA[2*i][2*j+1]),
                          add2(sA[2*i+1][2*j], sA[2*i+1][2*j+1])), quarter);
        scr1[tid] = s;
        g_s1[(size_t)nc * 65536 + (size_t)(by * 16 + i) * 256 + (bx * 16 + j)] = s;
    }
    __syncthreads();
    if (tid < 64) {
        int i = tid >> 3, j = tid & 7;
        u64 s = mul2(add2(add2(scr1[(2*i)*16 + 2*j], scr1[(2*i)*16 + 2*j + 1]),
                          add2(scr1[(2*i+1)*16 + 2*j], scr1[(2*i+1)*16 + 2*j + 1])), quarter);
        scr2[tid] = s;
        g_s2[(size_t)nc * 16384 + (size_t)(by * 8 + i) * 128 + (bx * 8 + j)] = s;
    }
    __syncthreads();
    if (tid < 16) {
        int i = tid >> 2, j = tid & 3;
        u64 s = mul2(add2(add2(scr2[(2*i)*8 + 2*j], scr2[(2*i)*8 + 2*j + 1]),
                          add2(scr2[(2*i+1)*8 + 2*j], scr2[(2*i+1)*8 + 2*j + 1])), quarter);
        scr3[tid] = s;
        g_s3[(size_t)nc * 4096 + (size_t)(by * 4 + i) * 64 + (bx * 4 + j)] = s;
    }
    __syncthreads();
    if (tid < 4) {
        int i = tid >> 1, j = tid & 1;
        u64 s = mul2(add2(add2(scr3[(2*i)*4 + 2*j], scr3[(2*i)*4 + 2*j + 1]),
                          add2(scr3[(2*i+1)*4 + 2*j], scr3[(2*i+1)*4 + 2*j + 1])), quarter);
        g_s4[(size_t)nc * 1024 + (size_t)(by * 2 + i) * 32 + (bx * 2 + j)] = s;
    }
}

// ======== scales 1-4 =========================================================
__global__ __launch_bounds__(256, 6) void ssim_rest(const float* __restrict__ win) {
    SSIM_SHARED
    int b = blockIdx.x;
    int D, O, nc, bx, by, scale;
    const u64* src;
    if (b < 3072)      { scale = 1; D = 256; O = 246; int l = b;        nc = l >> 6; int r = l & 63; by = r >> 3; bx = r & 7; src = g_s1; }
    else if (b < 3840) { scale = 2; D = 128; O = 118; int l = b - 3072; nc = l >> 4; int r = l & 15; by = r >> 2; bx = r & 3; src = g_s2; }
    else if (b < 4032) { scale = 3; D = 64;  O = 54;  int l = b - 3840; nc = l >> 2; int r = l & 3;  by = r >> 1; bx = r & 1; src = g_s3; }
    else               { scale = 4; D = 32;  O = 22;  int l = b - 4032; nc = l;      by = 0;         bx = 0;      src = g_s4; }
    src += (size_t)nc * D * D;
    int ox0 = bx * 32, oy0 = by * 32;
    int tid = threadIdx.y * 32 + threadIdx.x;

    SSIM_TAPS

    // vectorized staging: 462 tasks, each 4 u64 cols via 2 LDG.128
#pragma unroll
    for (int it = 0; it < 2; it++) {
        int t = tid + it * 256;
        if (t < 462) {
            int r = t / 11;
            int g = t - r * 11;
            int gy = oy0 + r;
            int gxq = ox0 + g * 4;
            ulonglong2 p0 = make_ulonglong2(0ull, 0ull), p1 = p0;
            if (gy < D && gxq < D) {   // D,gxq multiples of 4: quad fully in-range
                const ulonglong2* rp = (const ulonglong2*)(src + (size_t)gy * D + gxq);
                p0 = rp[0]; p1 = rp[1];
            }
            ulonglong2* dst = (ulonglong2*)&sA[r][g * 4];
            dst[0] = p0; dst[1] = p1;
        }
    }
    __syncthreads();

    SSIM_WP
    SSIM_HORIZ_TASK(tid)
    if (tid < 80) SSIM_HORIZ_TASK(tid + 256)
    __syncthreads();

    SSIM_VERT_AND_REDUCE(O, scale)
}

// ---------------- final ------------------------------------------------------
__global__ void final_kernel(const float* __restrict__ weights, float* __restrict__ out) {
    __shared__ float vals[NC];
    int t = threadIdx.x;
    const int Os[5] = {502, 246, 118, 54, 22};
    if (t < NC) {
        float prod = 1.f;
#pragma unroll
        for (int s = 0; s < 5; s++) {
            float inv = 1.f / ((float)Os[s] * (float)Os[s]);
            float m = (s < 4) ? g_cs_sum[s][t] : g_ssim_sum[s][t];
            m *= inv;
            if (s < 4) m = fmaxf(m, 0.f);
            prod *= powf(m, weights[s]);
        }
        vals[t] = prod;
    }
    __syncthreads();
    if (t == 0) {
        float s = 0.f;
        for (int i = 0; i < NC; i++) s += vals[i];
        out[0] = s / (float)NC;
    }
}

// ---------------- launch -----------------------------------------------------
extern "C" void kernel_launch(void* const* d_in, const int* in_sizes, int n_in,
                              void* d_out, int out_size) {
    const float* x   = (const float*)d_in[0];
    const float* y   = (const float*)d_in[1];
    const float* win = (const float*)d_in[2];
    const float* wts = (const float*)d_in[3];
    float* out = (float*)d_out;

    init_kernel<<<1, 256>>>();
    ssim_scale0<<<12288, dim3(32, 8)>>>(x, y, win);
    ssim_rest<<<4080, dim3(32, 8)>>>(win);
    final_kernel<<<1, 64>>>(wts, out);
}

// round 11
// speedup vs baseline: 1.8383x; 1.0036x over previous
#include <cuda_runtime.h>

#define WS    11
#define TILE  32
#define IN    42
#define SAPAD 46
#define HPAD  33
#define NC    48

#define SA_BYTES (IN * SAPAD * 8)      // 15456
#define HC_BYTES (IN * HPAD * 16)      // 22176

typedef unsigned long long u64;

// ---------------- packed f32x2 helpers --------------------------------------
__device__ __forceinline__ u64 pack2(float lo, float hi) {
    u64 r; asm("mov.b64 %0, {%1, %2};" : "=l"(r) : "f"(lo), "f"(hi)); return r;
}
__device__ __forceinline__ float2 unpack2(u64 v) {
    float2 f; asm("mov.b64 {%0, %1}, %2;" : "=f"(f.x), "=f"(f.y) : "l"(v)); return f;
}
__device__ __forceinline__ u64 fma2(u64 a, u64 b, u64 c) {
    u64 d; asm("fma.rn.f32x2 %0, %1, %2, %3;" : "=l"(d) : "l"(a), "l"(b), "l"(c)); return d;
}
__device__ __forceinline__ u64 add2(u64 a, u64 b) {
    u64 d; asm("add.rn.f32x2 %0, %1, %2;" : "=l"(d) : "l"(a), "l"(b)); return d;
}
__device__ __forceinline__ u64 mul2(u64 a, u64 b) {
    u64 d; asm("mul.rn.f32x2 %0, %1, %2;" : "=l"(d) : "l"(a), "l"(b)); return d;
}

// ---------------- scratch ----------------------------------------------------
// Zero-initialized at module load; final_kernel re-zeroes after consuming, so
// every graph replay starts from zeros (deterministic).
__device__ float g_cs_sum[5][NC];
__device__ float g_ssim_sum[5][NC];
__device__ u64 g_s1[NC * 256 * 256];   // interleaved (x,y)
__device__ u64 g_s2[NC * 128 * 128];
__device__ u64 g_s3[NC * 64 * 64];
__device__ u64 g_s4[NC * 32 * 32];

// ======== ssim core pieces ===================================================
#define SSIM_SHARED \
    __shared__ __align__(16) char smem_raw[SA_BYTES + HC_BYTES]; \
    u64 (*sA)[SAPAD] = reinterpret_cast<u64(*)[SAPAD]>(smem_raw); \
    ulonglong2 (*hC)[HPAD] = reinterpret_cast<ulonglong2(*)[HPAD]>(smem_raw + SA_BYTES); \
    __shared__ float tg_s[WS]; \
    __shared__ float red[16];

#define SSIM_TAPS \
    if (tid < WS) tg_s[tid] = win[tid * WS + 5] * rsqrtf(win[5 * WS + 5]);

#define SSIM_WP \
    u64 wp[6]; \
    _Pragma("unroll") \
    for (int k = 0; k < 6; k++) { float w = tg_s[k]; wp[k] = pack2(w, w); }

#define WSYM(k) wp[(k) < 6 ? (k) : 10 - (k)]

#define SSIM_HORIZ_TASK(t) { \
    int c0g = (t) / 42; \
    int r   = (t) - c0g * 42; \
    int c0  = c0g * 4; \
    u64 a1v[4] = {0,0,0,0}, a2v[4] = {0,0,0,0}; \
    const ulonglong2* hp = (const ulonglong2*)&sA[r][0] + (c0 >> 1); \
    ulonglong2 pr = hp[0]; \
    _Pragma("unroll") \
    for (int jp = 0; jp < 7; jp++) { \
        ulonglong2 nxt; \
        if (jp < 6) nxt = hp[jp + 1]; \
        _Pragma("unroll") \
        for (int e = 0; e < 2; e++) { \
            int j = 2 * jp + e; \
            u64 a = e ? pr.y : pr.x; \
            float2 v = unpack2(a); \
            u64 q = pack2(fmaf(v.x, v.x, v.y * v.y), v.x * v.y); \
            _Pragma("unroll") \
            for (int o = 0; o < 4; o++) { \
                int k = j - o; \
                if (k >= 0 && k < WS) { \
                    a1v[o] = fma2(WSYM(k), a, a1v[o]); \
                    a2v[o] = fma2(WSYM(k), q, a2v[o]); \
                } \
            } \
        } \
        pr = nxt; \
    } \
    _Pragma("unroll") \
    for (int o = 0; o < 4; o++) hC[r][c0 + o] = make_ulonglong2(a1v[o], a2v[o]); \
}

#define SSIM_VERT_AND_REDUCE(OVAL, SCALE) \
    float ssim_acc = 0.f, cs_acc = 0.f; \
    { \
        int c = threadIdx.x; \
        int rbase = threadIdx.y * 4; \
        u64 a1v[4] = {0,0,0,0}, a2v[4] = {0,0,0,0}; \
        const ulonglong2* vp = &hC[rbase][c]; \
        ulonglong2 hv = vp[0]; \
        _Pragma("unroll") \
        for (int j = 0; j < 14; j++) { \
            ulonglong2 nxt; \
            if (j < 13) nxt = vp[(j + 1) * HPAD]; \
            _Pragma("unroll") \
            for (int o = 0; o < 4; o++) { \
                int k = j - o; \
                if (k >= 0 && k < WS) { \
                    a1v[o] = fma2(WSYM(k), hv.x, a1v[o]); \
                    a2v[o] = fma2(WSYM(k), hv.y, a2v[o]); \
                } \
            } \
            hv = nxt; \
        } \
        bool colv = (ox0 + c) < (OVAL); \
        _Pragma("unroll") \
        for (int o = 0; o < 4; o++) { \
            if (colv && (oy0 + rbase + o) < (OVAL)) { \
                float2 m = unpack2(a1v[o]); \
                float2 e = unpack2(a2v[o]); \
                float mxx = m.x * m.x, myy = m.y * m.y, mxy = m.x * m.y; \
                float svar = e.x - mxx - myy; \
                float sxy_ = e.y - mxy; \
                const float C1 = 1e-4f, C2 = 9e-4f; \
                float cs = __fdividef(2.f * sxy_ + C2, svar + C2); \
                float ss = __fdividef(2.f * mxy + C1, mxx + myy + C1) * cs; \
                cs_acc += cs; ssim_acc += ss; \
            } \
        } \
    } \
    _Pragma("unroll") \
    for (int o = 16; o > 0; o >>= 1) { \
        ssim_acc += __shfl_down_sync(0xffffffffu, ssim_acc, o); \
        cs_acc   += __shfl_down_sync(0xffffffffu, cs_acc, o); \
    } \
    if (threadIdx.x == 0) { red[threadIdx.y] = ssim_acc; red[8 + threadIdx.y] = cs_acc; } \
    __syncthreads(); \
    if (tid == 0) { \
        float s = 0.f, cc = 0.f; \
        _Pragma("unroll") \
        for (int i = 0; i < 8; i++) { s += red[i]; cc += red[8 + i]; } \
        atomicAdd(&g_ssim_sum[SCALE][nc], s); \
        atomicAdd(&g_cs_sum[SCALE][nc], cc); \
    }

// ======== scale 0: ssim + full pool chain in the tail =======================
__global__ __launch_bounds__(256, 6) void ssim_scale0(
    const float* __restrict__ x0, const float* __restrict__ y0,
    const float* __restrict__ win) {
    SSIM_SHARED
    int b = blockIdx.x;
    int nc = b >> 8;
    int r0 = b & 255;
    int by = r0 >> 4, bx = r0 & 15;
    const float* xb = x0 + (size_t)nc * 262144;
    const float* yb = y0 + (size_t)nc * 262144;
    int ox0 = bx * 32, oy0 = by * 32;
    int tid = threadIdx.y * 32 + threadIdx.x;

    SSIM_TAPS

#pragma unroll
    for (int it = 0; it < 2; it++) {
        int t = tid + it * 256;
        if (t < 462) {
            int r = t / 11;
            int g = t - r * 11;
            int gy = oy0 + r;
            int gxq = ox0 + g * 4;
            float4 xq = make_float4(0.f, 0.f, 0.f, 0.f), yq = xq;
            if (gy < 512 && gxq < 512) {
                xq = *(const float4*)(xb + (size_t)gy * 512 + gxq);
                yq = *(const float4*)(yb + (size_t)gy * 512 + gxq);
            }
            ulonglong2* dst = (ulonglong2*)&sA[r][g * 4];
            dst[0] = make_ulonglong2(pack2(xq.x, yq.x), pack2(xq.y, yq.y));
            dst[1] = make_ulonglong2(pack2(xq.z, yq.z), pack2(xq.w, yq.w));
        }
    }
    __syncthreads();

    SSIM_WP
    SSIM_HORIZ_TASK(tid)
    if (tid < 80) SSIM_HORIZ_TASK(tid + 256)
    __syncthreads();

    SSIM_VERT_AND_REDUCE(502, 0)

    // ---- pool chain tail: sA intact; hC dead -> reuse as scratch ----
    u64* scr1 = (u64*)(smem_raw + SA_BYTES);
    u64* scr2 = scr1 + 256;
    u64* scr3 = scr2 + 64;
    u64 quarter = pack2(0.25f, 0.25f);
    {
        int i = tid >> 4, j = tid & 15;
        u64 s = mul2(add2(add2(sA[2*i][2*j], sA[2*i][2*j+1]),
                          add2(sA[2*i+1][2*j], sA[2*i+1][2*j+1])), quarter);
        scr1[tid] = s;
        g_s1[(size_t)nc * 65536 + (size_t)(by * 16 + i) * 256 + (bx * 16 + j)] = s;
    }
    __syncthreads();
    if (tid < 64) {
        int i = tid >> 3, j = tid & 7;
        u64 s = mul2(add2(add2(scr1[(2*i)*16 + 2*j], scr1[(2*i)*16 + 2*j + 1]),
                          add2(scr1[(2*i+1)*16 + 2*j], scr1[(2*i+1)*16 + 2*j + 1])), quarter);
        scr2[tid] = s;
        g_s2[(size_t)nc * 16384 + (size_t)(by * 8 + i) * 128 + (bx * 8 + j)] = s;
    }
    __syncthreads();
    if (tid < 16) {
        int i = tid >> 2, j = tid & 3;
        u64 s = mul2(add2(add2(scr2[(2*i)*8 + 2*j], scr2[(2*i)*8 + 2*j + 1]),
                          add2(scr2[(2*i+1)*8 + 2*j], scr2[(2*i+1)*8 + 2*j + 1])), quarter);
        scr3[tid] = s;
        g_s3[(size_t)nc * 4096 + (size_t)(by * 4 + i) * 64 + (bx * 4 + j)] = s;
    }
    __syncthreads();
    if (tid < 4) {
        int i = tid >> 1, j = tid & 1;
        u64 s = mul2(add2(add2(scr3[(2*i)*4 + 2*j], scr3[(2*i)*4 + 2*j + 1]),
                          add2(scr3[(2*i+1)*4 + 2*j], scr3[(2*i+1)*4 + 2*j + 1])), quarter);
        g_s4[(size_t)nc * 1024 + (size_t)(by * 2 + i) * 32 + (bx * 2 + j)] = s;
    }
}

// ======== scales 1-4 =========================================================
__global__ __launch_bounds__(256, 6) void ssim_rest(const float* __restrict__ win) {
    SSIM_SHARED
    int b = blockIdx.x;
    int D, O, nc, bx, by, scale;
    const u64* src;
    if (b < 3072)      { scale = 1; D = 256; O = 246; int l = b;        nc = l >> 6; int r = l & 63; by = r >> 3; bx = r & 7; src = g_s1; }
    else if (b < 3840) { scale = 2; D = 128; O = 118; int l = b - 3072; nc = l >> 4; int r = l & 15; by = r >> 2; bx = r & 3; src = g_s2; }
    else if (b < 4032) { scale = 3; D = 64;  O = 54;  int l = b - 3840; nc = l >> 2; int r = l & 3;  by = r >> 1; bx = r & 1; src = g_s3; }
    else               { scale = 4; D = 32;  O = 22;  int l = b - 4032; nc = l;      by = 0;         bx = 0;      src = g_s4; }
    src += (size_t)nc * D * D;
    int ox0 = bx * 32, oy0 = by * 32;
    int tid = threadIdx.y * 32 + threadIdx.x;

    SSIM_TAPS

#pragma unroll
    for (int it = 0; it < 2; it++) {
        int t = tid + it * 256;
        if (t < 462) {
            int r = t / 11;
            int g = t - r * 11;
            int gy = oy0 + r;
            int gxq = ox0 + g * 4;
            ulonglong2 p0 = make_ulonglong2(0ull, 0ull), p1 = p0;
            if (gy < D && gxq < D) {
                const ulonglong2* rp = (const ulonglong2*)(src + (size_t)gy * D + gxq);
                p0 = rp[0]; p1 = rp[1];
            }
            ulonglong2* dst = (ulonglong2*)&sA[r][g * 4];
            dst[0] = p0; dst[1] = p1;
        }
    }
    __syncthreads();

    SSIM_WP
    SSIM_HORIZ_TASK(tid)
    if (tid < 80) SSIM_HORIZ_TASK(tid + 256)
    __syncthreads();

    SSIM_VERT_AND_REDUCE(O, scale)
}

// ---------------- final: parallel pow, product, mean; then re-zero ----------
__global__ void final_kernel(const float* __restrict__ weights, float* __restrict__ out) {
    __shared__ float pw[5][NC];
    __shared__ float vals[NC];
    int t = threadIdx.x;
    const float invA[5] = {1.f/(502.f*502.f), 1.f/(246.f*246.f), 1.f/(118.f*118.f),
                           1.f/(54.f*54.f),   1.f/(22.f*22.f)};
    if (t < 5 * NC) {
        int s = t / NC, i = t - s * NC;
        float m = (s < 4) ? g_cs_sum[s][i] : g_ssim_sum[s][i];
        m *= invA[s];
        if (s < 4) m = fmaxf(m, 0.f);
        pw[s][i] = __powf(m, weights[s]);
    }
    __syncthreads();
    // re-zero accumulators for the next graph replay
    if (t < 5 * NC) { (&g_cs_sum[0][0])[t] = 0.f; (&g_ssim_sum[0][0])[t] = 0.f; }
    if (t < NC) {
        float p = pw[0][t] * pw[1][t] * pw[2][t] * pw[3][t] * pw[4][t];
        vals[t] = p;
    }
    __syncthreads();
    if (t < 32) {
        float s = vals[t] + ((t < 16) ? vals[t + 32] : 0.f);
#pragma unroll
        for (int o = 16; o > 0; o >>= 1) s += __shfl_down_sync(0xffffffffu, s, o);
        if (t == 0) out[0] = s / (float)NC;
    }
}

// ---------------- launch -----------------------------------------------------
extern "C" void kernel_launch(void* const* d_in, const int* in_sizes, int n_in,
                              void* d_out, int out_size) {
    const float* x   = (const float*)d_in[0];
    const float* y   = (const float*)d_in[1];
    const float* win = (const float*)d_in[2];
    const float* wts = (const float*)d_in[3];
    float* out = (float*)d_out;

    ssim_scale0<<<12288, dim3(32, 8)>>>(x, y, win);
    ssim_rest<<<4080, dim3(32, 8)>>>(win);
    final_kernel<<<1, 256>>>(wts, out);
}